// round 11
// baseline (speedup 1.0000x reference)
#include <cuda_runtime.h>

#define SZ   256          // image size
#define NT   256          // number of triangles
#define QSTRIDE 5         // float4 per triangle record (80B: kills bank conflicts)
#define LCAP (NT + 8)     // list capacity incl. null padding

// Per-triangle record layout (float4 index, stride 5, 80 B):
//  q0 : pAB edge: ax(=v1x), ay(=v1y), dy(=v0y-v1y), dx(=v0x-v1x)
//  q1 : pCB edge: ax(=v2x), ay(=v2y), dy(=v1y-v2y), dx(=v1x-v2x)
//  q2 : pCA edge: ax(=v0x), ay(=v0y), dy(=v2y-v0y), dx(=v2x-v0x)
//  q3 : invw, z0, z1, z2
//  q4 : pad (written zero)
// Slot NT is an all-zero "null" record: prod==0 -> never taken. Both lists
// are pre-filled with null offsets, so entries past cnt are harmless and the
// x2-unrolled loop needs no tail guard.
//
// Block: 256 threads process TWO stacked 8x8 tiles (rows iy0..iy0+7 and
// iy0+8..iy0+15) with INDEPENDENT per-tile cull lists: the triangle records
// are built once per block (prep replication halves vs one-tile blocks) but
// cnt per loop stays at the small 8x8 level (the R7 16x8 tile inflated cnt).
// 64 pixels x 4 slices per tile; warp = pixel row, lane = slice*8 + col.
// Grid: (32, 16) = 512 blocks <= 740 resident @ 5 CTAs/SM -> single wave.
//
// The z-buffer scan reduces to an argmax over covering triangles with ties
// broken by larger triangle index ('inside' => all barycentric weights > 0 =>
// z is a convex combination of vertex z's => z >= global zmin, so the zbuf
// init never matters for covered pixels). Argmax is order-independent:
// the candidate lists need NO ordering (tie-break uses the stored offset,
// monotone in triangle index), and slices merge by shuffle reduction.
//
// Edge culling: each edge function e(p) is affine in p, so over the tile
// rectangle its max is at a corner. If any edge's corner-max <= -1e-5
// (rounding of O(1) fp32 values is < 1e-6), no pixel in the tile can have
// all three edge values strictly positive -> triangle cannot win any pixel.
// The x-corner term is shared between the two tiles; only y-terms differ.
//
// NOTE: the inside-test arithmetic form (px-ax)*dy-(py-ay)*dx must match the
// reference exactly — refactoring it flips boundary pixels and fails 1e-3.
__global__ __launch_bounds__(256, 5)
void render_kernel(const float* __restrict__ tris,
                   const float* __restrict__ uvs,
                   const float* __restrict__ uvmap,
                   float* __restrict__ out) {
    __shared__ __align__(16) float4 s_q[(NT + 1) * QSTRIDE];  // ~20.6 KB
    __shared__ unsigned short s_listA[LCAP];
    __shared__ unsigned short s_listB[LCAP];
    __shared__ int s_cntA, s_cntB;

    int tid   = threadIdx.x;
    int lane  = tid & 31;
    int warp  = tid >> 5;
    int slice = lane >> 3;        // 0..3
    int pcol  = lane & 7;         // 0..7

    const float d = 2.0f / 255.0f;
    const unsigned short NULLOFF = (unsigned short)(NT * QSTRIDE);

    // ---- phase 0: zero counters, null record, null-fill both lists ----
    if (tid == 0) { s_cntA = 0; s_cntB = 0; }
    if (tid < QSTRIDE)
        s_q[NT * QSTRIDE + tid] = make_float4(0.0f, 0.0f, 0.0f, 0.0f);
    s_listA[tid] = NULLOFF;
    s_listB[tid] = NULLOFF;
    if (tid < LCAP - NT) { s_listA[NT + tid] = NULLOFF; s_listB[NT + tid] = NULLOFF; }

    // Tile corner coordinates, computed with the exact per-pixel formula.
    int jx0 = blockIdx.x * 8,  jx1 = jx0 + 7;
    int iy0 = blockIdx.y * 16;                 // tile A rows iy0..+7, B +8..+15
    float cx0  = -1.0f + (float)jx0 * d;
    float cx1  = -1.0f + (float)jx1 * d;
    float cyA0 =  1.0f - (float)iy0 * d;        // tile A max y
    float cyA1 =  1.0f - (float)(iy0 + 7) * d;  // tile A min y
    float cyB0 =  1.0f - (float)(iy0 + 8) * d;  // tile B max y
    float cyB1 =  1.0f - (float)(iy0 + 15) * d; // tile B min y

    // ---- phase 1: thread t builds triangle t's record + per-tile cull ----
    bool keepA, keepB;
    {
        const float* T = tris + tid * 9;
        float v0x = __ldg(T + 0), v0y = __ldg(T + 1), v0z = __ldg(T + 2);
        float v1x = __ldg(T + 3), v1y = __ldg(T + 4), v1z = __ldg(T + 5);
        float v2x = __ldg(T + 6), v2y = __ldg(T + 7), v2z = __ldg(T + 8);

        float w = (v1x - v0x) * (v2y - v0y) - (v1y - v0y) * (v2x - v0x);
        bool valid = (w >= 1e-9f);
        float ws = valid ? w : 1.0f;
        float invw = 1.0f / ws;

        float4* Q = s_q + tid * QSTRIDE;
        Q[0] = make_float4(v1x, v1y, v0y - v1y, v0x - v1x);
        Q[1] = make_float4(v2x, v2y, v1y - v2y, v1x - v2x);
        Q[2] = make_float4(v0x, v0y, v2y - v0y, v2x - v0x);
        Q[3] = make_float4(invw, v0z, v1z, v2z);
        Q[4] = make_float4(0.0f, 0.0f, 0.0f, 0.0f);

        // Edge corner-max cull, x-term shared across the two tiles:
        // e = (cx-ax)*dy - (cy-ay)*dx;  max = max_x[(cx-ax)*dy] + max_y[-(cy-ay)*dx]
        #define XTERM(ax, dy)      fmaxf((cx0 - (ax)) * (dy), (cx1 - (ax)) * (dy))
        #define YTERM(ay, dx, c0, c1) fmaxf(-(((c0) - (ay)) * (dx)), -(((c1) - (ay)) * (dx)))
        float xAB = XTERM(v1x, v0y - v1y);
        float xCB = XTERM(v2x, v1y - v2y);
        float xCA = XTERM(v0x, v2y - v0y);
        float aAB = xAB + YTERM(v1y, v0x - v1x, cyA0, cyA1);
        float aCB = xCB + YTERM(v2y, v1x - v2x, cyA0, cyA1);
        float aCA = xCA + YTERM(v0y, v2x - v0x, cyA0, cyA1);
        float bAB = xAB + YTERM(v1y, v0x - v1x, cyB0, cyB1);
        float bCB = xCB + YTERM(v2y, v1x - v2x, cyB0, cyB1);
        float bCA = xCA + YTERM(v0y, v2x - v0x, cyB0, cyB1);
        #undef XTERM
        #undef YTERM

        keepA = valid && (aAB > -1e-5f) && (aCB > -1e-5f) && (aCA > -1e-5f);
        keepB = valid && (bAB > -1e-5f) && (bCB > -1e-5f) && (bCA > -1e-5f);
    }

    // Unordered compaction for both lists (counters zeroed & lists nulled in
    // phase 0; the sync below orders phase 0 before these atomics/writes).
    __syncthreads();
    {
        unsigned mA = __ballot_sync(0xffffffffu, keepA);
        unsigned mB = __ballot_sync(0xffffffffu, keepB);
        int baseA = 0, baseB = 0;
        if (lane == 0) {
            if (mA) baseA = atomicAdd(&s_cntA, __popc(mA));
            if (mB) baseB = atomicAdd(&s_cntB, __popc(mB));
        }
        baseA = __shfl_sync(0xffffffffu, baseA, 0);
        baseB = __shfl_sync(0xffffffffu, baseB, 0);
        unsigned short myoff = (unsigned short)(tid * QSTRIDE);
        if (keepA) s_listA[baseA + __popc(mA & ((1u << lane) - 1u))] = myoff;
        if (keepB) s_listB[baseB + __popc(mB & ((1u << lane) - 1u))] = myoff;
    }
    __syncthreads();
    int cntA = s_cntA;
    int cntB = s_cntB;

    // Pixel coordinates: pts[i][j] = (lin[j], lin[255-i]), lin[k] = -1 + k*2/255
    int j  = jx0 + pcol;
    int iA = iy0 + warp;
    float px  = -1.0f + (float)j * d;
    float pyA =  1.0f - (float)iA * d;
    float pyB =  1.0f - (float)(iA + 8) * d;

    // Branch-free EVAL, identical FP forms to the reference. Tie-break
    // (z equal) -> larger stored offset == larger triangle index.
    #define EVAL(OFF, PY)                                                    \
    {                                                                        \
        int off = (OFF);                                                     \
        float4 q0 = s_q[off], q1 = s_q[off + 1],                             \
               q2 = s_q[off + 2], q3 = s_q[off + 3];                         \
        float pAB = (px - q0.x) * q0.z - ((PY) - q0.y) * q0.w;               \
        float pCB = (px - q1.x) * q1.z - ((PY) - q1.y) * q1.w;               \
        float pCA = (px - q2.x) * q2.z - ((PY) - q2.y) * q2.w;               \
        float prod = fmaxf(pAB, 0.0f) * fmaxf(pCB, 0.0f) * fmaxf(pCA, 0.0f); \
        float w1 = pCB * q3.x;                                               \
        float w2 = pCA * q3.x;                                               \
        float w3 = 1.0f - w1 - w2;                                           \
        float z  = w1 * q3.y + w2 * q3.z + w3 * q3.w;                        \
        bool take = (prod > 0.0f) &&                                         \
                    ((z > zb) || ((z == zb) && (off > bi)));                 \
        zb  = take ? z   : zb;                                               \
        bi  = take ? off : bi;                                               \
        w1s = take ? w1  : w1s;                                              \
        w2s = take ? w2  : w2s;                                              \
    }

    float w1A, w2A; int biA;
    float w1B, w2B; int biB;

    // ---- tile A ----
    {
        float zb = -3.402823466e+38f, w1s = 0.0f, w2s = 0.0f;
        int bi = -1;
        for (int k = slice; k < cntA; k += 8) {
            int offA = s_listA[k];
            int offB = s_listA[k + 4];
            EVAL(offA, pyA);
            EVAL(offB, pyA);
        }
        #pragma unroll
        for (int off = 8; off < 32; off <<= 1) {
            float oz = __shfl_down_sync(0xffffffffu, zb, off);
            int   oi = __shfl_down_sync(0xffffffffu, bi, off);
            float o1 = __shfl_down_sync(0xffffffffu, w1s, off);
            float o2 = __shfl_down_sync(0xffffffffu, w2s, off);
            bool take = (oz > zb) || ((oz == zb) && (oi > bi));
            if (take) { zb = oz; bi = oi; w1s = o1; w2s = o2; }
        }
        w1A = w1s; w2A = w2s; biA = bi;
    }

    // ---- tile B ----
    {
        float zb = -3.402823466e+38f, w1s = 0.0f, w2s = 0.0f;
        int bi = -1;
        for (int k = slice; k < cntB; k += 8) {
            int offA = s_listB[k];
            int offB = s_listB[k + 4];
            EVAL(offA, pyB);
            EVAL(offB, pyB);
        }
        #pragma unroll
        for (int off = 8; off < 32; off <<= 1) {
            float oz = __shfl_down_sync(0xffffffffu, zb, off);
            int   oi = __shfl_down_sync(0xffffffffu, bi, off);
            float o1 = __shfl_down_sync(0xffffffffu, w1s, off);
            float o2 = __shfl_down_sync(0xffffffffu, w2s, off);
            bool take = (oz > zb) || ((oz == zb) && (oi > bi));
            if (take) { zb = oz; bi = oi; w1s = o1; w2s = o2; }
        }
        w1B = w1s; w2B = w2s; biB = bi;
    }
    #undef EVAL

    if (slice == 0) {
        // Deferred UV interpolation + bilinear texture sample, both pixels.
        #pragma unroll
        for (int t = 0; t < 2; t++) {
            int   bi  = t ? biB : biA;
            float w1s = t ? w1B : w1A;
            float w2s = t ? w2B : w2A;

            float r = 0.0f, g = 0.0f, b = 0.0f, a = 0.0f;
            if (bi >= 0) {
                a = 1.0f;
                const float* U = uvs + (bi / QSTRIDE) * 6;
                float u0 = __ldg(U + 0) * 2.0f - 1.0f, v0 = __ldg(U + 1) * 2.0f - 1.0f;
                float u1 = __ldg(U + 2) * 2.0f - 1.0f, v1 = __ldg(U + 3) * 2.0f - 1.0f;
                float u2 = __ldg(U + 4) * 2.0f - 1.0f, v2 = __ldg(U + 5) * 2.0f - 1.0f;
                float w3 = 1.0f - w1s - w2s;
                float uu = w1s * u0 + w2s * u1 + w3 * u2;
                float vv = w1s * v0 + w2s * v1 + w3 * v2;

                float x = (uu + 1.0f) * 0.5f * 1023.0f;
                float y = (vv + 1.0f) * 0.5f * 1023.0f;
                float x0f = floorf(x);
                float y0f = floorf(y);
                float wx = x - x0f;
                float wy = y - y0f;
                #pragma unroll
                for (int cy = 0; cy < 2; cy++) {
                    #pragma unroll
                    for (int cx = 0; cx < 2; cx++) {
                        float ix = x0f + (float)cx;
                        float iy = y0f + (float)cy;
                        bool inb = (ix >= 0.0f) && (ix <= 1023.0f) &&
                                   (iy >= 0.0f) && (iy <= 1023.0f);
                        if (inb) {
                            int ii = (int)ix;
                            int jj = (int)iy;
                            float wgt = (cx ? wx : 1.0f - wx) * (cy ? wy : 1.0f - wy);
                            int toff = jj * 1024 + ii;
                            r += __ldg(uvmap + toff) * wgt;
                            g += __ldg(uvmap + 1048576 + toff) * wgt;
                            b += __ldg(uvmap + 2097152 + toff) * wgt;
                        }
                    }
                }
            }

            int pix = (iA + t * 8) * SZ + j;
            out[pix]              = r;
            out[65536 + pix]      = g;
            out[2 * 65536 + pix]  = b;
            out[3 * 65536 + pix]  = a;
        }
    }
}

extern "C" void kernel_launch(void* const* d_in, const int* in_sizes, int n_in,
                              void* d_out, int out_size) {
    const float* tris  = (const float*)d_in[0];   // (256,3,3)
    const float* uvs   = (const float*)d_in[1];   // (256,3,2)
    const float* uvmap = (const float*)d_in[2];   // (3,1024,1024)
    float* out = (float*)d_out;                   // (4,256,256)

    dim3 block(256);
    dim3 grid(SZ / 8, SZ / 16);
    render_kernel<<<grid, block>>>(tris, uvs, uvmap, out);
}